// round 5
// baseline (speedup 1.0000x reference)
#include <cuda_runtime.h>
#include <math.h>

// ---------------------------------------------------------------------------
// RPN forward, batch -1 only.
// Pipeline: pad -> weight transpose -> 3x3 conv (implicit GEMM, fp32) ->
//           1x1 heads + decode + sort-key -> O(N^2) stable rank (top 6000) ->
//           NMS mask (replicating reference's yy2=max bug) -> serial scan ->
//           stable selection -> 300x4 output.
// ---------------------------------------------------------------------------

#define FSZ   50
#define XP    52
#define NCH   512
#define NKEYS 22500           // 2500 * 9 anchors
#define PRE_NMS 6000
#define POST_NMS 300
#define NWORDS 188            // ceil(6000/32)

// __device__ scratch (allocation-free rule)
__device__ float  g_Xp[NCH * XP * XP];                 // padded input, batch 7
__device__ float  g_Wt[9 * NCH * NCH];                 // [tap][ic][oc]
__device__ float  g_feat[FSZ * FSZ * NCH];             // [s][oc] after leaky relu
__device__ unsigned long long g_keys[NKEYS];
__device__ float4 g_boxes[NKEYS];
__device__ float4 g_sboxes[PRE_NMS];
__device__ unsigned g_mask[PRE_NMS * NWORDS];

// ---------------------------------------------------------------------------
__global__ void pad_kernel(const float* __restrict__ in) {
    int idx = blockIdx.x * blockDim.x + threadIdx.x;
    if (idx >= NCH * XP * XP) return;
    int c = idx / (XP * XP);
    int r = idx - c * (XP * XP);
    int y = r / XP, x = r - y * XP;
    float v = 0.0f;
    if (y >= 1 && y <= FSZ && x >= 1 && x <= FSZ)
        v = in[((7 * NCH + c) * FSZ + (y - 1)) * FSZ + (x - 1)];
    g_Xp[idx] = v;
}

// conv_w[oc][ic][kh][kw] -> g_Wt[tap][ic][oc]
__global__ void wt_kernel(const float* __restrict__ w) {
    int idx = blockIdx.x * blockDim.x + threadIdx.x;
    if (idx >= NCH * NCH * 9) return;
    int tap = idx % 9;
    int ic  = (idx / 9) % NCH;
    int oc  = idx / (9 * NCH);
    g_Wt[(tap * NCH + ic) * NCH + oc] = w[idx];
}

// ---------------------------------------------------------------------------
// 3x3 conv: block = 64 oc x 50 w (one row h). 160 threads: 16 oc-quads x 10 w-groups(5).
// K loop over ic tiles of 8, taps unrolled. Output: g_feat[s][oc], leaky relu applied.
// ---------------------------------------------------------------------------
__global__ void __launch_bounds__(160) conv_kernel(const float* __restrict__ bias) {
    const int h   = blockIdx.y;
    const int ocb = blockIdx.x * 64;
    const int tid = threadIdx.x;
    const int to  = tid & 15;          // oc quad index
    const int tw  = tid >> 4;          // 0..9, w group of 5
    const int wb  = tw * 5;

    __shared__ float As[8 * 9 * 64];   // [t*9+tap][oc]  (18 KB)
    __shared__ float Bs[8 * 3 * 52];   // [t][kh][x]     (4.9 KB)

    float acc[4][5];
#pragma unroll
    for (int r = 0; r < 4; ++r)
#pragma unroll
        for (int j = 0; j < 5; ++j) acc[r][j] = 0.0f;

    for (int ic0 = 0; ic0 < NCH; ic0 += 8) {
        // load A: 1152 float4
#pragma unroll
        for (int it = 0; it < 8; ++it) {
            int idx = tid + it * 160;
            if (idx < 1152) {
                int rrow = idx >> 4, col = idx & 15;
                int t = rrow / 9, tap = rrow - t * 9;
                const float4* src = reinterpret_cast<const float4*>(
                    &g_Wt[(tap * NCH + ic0 + t) * NCH + ocb]);
                reinterpret_cast<float4*>(As)[idx] = src[col];
            }
        }
        // load B: 1248 floats
#pragma unroll
        for (int it = 0; it < 8; ++it) {
            int idx = tid + it * 160;
            if (idx < 1248) {
                int t = idx / 156;
                int rem = idx - t * 156;
                int kh = rem / 52, x = rem - kh * 52;
                Bs[idx] = g_Xp[(ic0 + t) * (XP * XP) + (h + kh) * XP + x];
            }
        }
        __syncthreads();

#pragma unroll 1
        for (int t = 0; t < 8; ++t) {
#pragma unroll
            for (int kh = 0; kh < 3; ++kh) {
                float b[7];
                const float* bp = &Bs[(t * 3 + kh) * 52 + wb];
#pragma unroll
                for (int j = 0; j < 7; ++j) b[j] = bp[j];
#pragma unroll
                for (int kw = 0; kw < 3; ++kw) {
                    float4 a4 = reinterpret_cast<const float4*>(As)[(t * 9 + kh * 3 + kw) * 16 + to];
#pragma unroll
                    for (int j = 0; j < 5; ++j) {
                        float bv = b[kw + j];
                        acc[0][j] += a4.x * bv;
                        acc[1][j] += a4.y * bv;
                        acc[2][j] += a4.z * bv;
                        acc[3][j] += a4.w * bv;
                    }
                }
            }
        }
        __syncthreads();
    }

    float4 bb = reinterpret_cast<const float4*>(bias)[(ocb >> 2) + to];
#pragma unroll
    for (int j = 0; j < 5; ++j) {
        int s = h * FSZ + wb + j;
        float4 v;
        v.x = acc[0][j] + bb.x;
        v.y = acc[1][j] + bb.y;
        v.z = acc[2][j] + bb.z;
        v.w = acc[3][j] + bb.w;
        v.x = (v.x >= 0.0f) ? v.x : 0.01f * v.x;
        v.y = (v.y >= 0.0f) ? v.y : 0.01f * v.y;
        v.z = (v.z >= 0.0f) ? v.z : 0.01f * v.z;
        v.w = (v.w >= 0.0f) ? v.w : 0.01f * v.w;
        *reinterpret_cast<float4*>(&g_feat[s * NCH + ocb + to * 4]) = v;
    }
}

// ---------------------------------------------------------------------------
// 1x1 heads + softmax score + anchor decode + sort key. One block per spatial s.
// ---------------------------------------------------------------------------
__global__ void __launch_bounds__(64) head_kernel(const float* __restrict__ rw,
                                                  const float* __restrict__ rb,
                                                  const float* __restrict__ cw,
                                                  const float* __restrict__ cb) {
    const int s = blockIdx.x;
    const int tid = threadIdx.x;
    __shared__ float f[NCH];
    __shared__ float vals[54];

    reinterpret_cast<float4*>(f)[tid]      = reinterpret_cast<const float4*>(&g_feat[s * NCH])[tid];
    reinterpret_cast<float4*>(f)[tid + 64] = reinterpret_cast<const float4*>(&g_feat[s * NCH])[tid + 64];
    __syncthreads();

    if (tid < 54) {
        const float* wr;
        float bv;
        if (tid < 36) { wr = rw + tid * NCH; bv = rb[tid]; }
        else          { wr = cw + (tid - 36) * NCH; bv = cb[tid - 36]; }
        float acc = 0.0f;
#pragma unroll 4
        for (int k = 0; k < NCH; k += 4) {
            float4 wv = *reinterpret_cast<const float4*>(wr + k);
            acc += wv.x * f[k];
            acc += wv.y * f[k + 1];
            acc += wv.z * f[k + 2];
            acc += wv.w * f[k + 3];
        }
        vals[tid] = acc + bv;
    }
    __syncthreads();

    if (tid < 9) {
        const int a = tid;
        float pr0 = vals[a * 4 + 0], pr1 = vals[a * 4 + 1];
        float pr2 = vals[a * 4 + 2], pr3 = vals[a * 4 + 3];
        float l0 = vals[36 + a * 2], l1 = vals[36 + a * 2 + 1];
        float m = fmaxf(l0, l1);
        float e0 = expf(l0 - m), e1 = expf(l1 - m);
        float score = e1 / (e0 + e1);

        int hh = s / FSZ, ww = s - hh * FSZ;
        float cx = (float)(16 * hh + 8);
        float cy = (float)(16 * ww + 8);
        int r = a / 3, q = a - r * 3;
        float basev = (q == 0) ? 128.0f : (q == 1 ? 256.0f : 512.0f);
        float sq_r  = (r == 0) ? sqrtf(0.5f) : (r == 1 ? 1.0f : sqrtf(2.0f)); // sqrt(rs)
        float sq_ir = (r == 0) ? sqrtf(2.0f) : (r == 1 ? 1.0f : sqrtf(0.5f)); // sqrt(1/rs)
        float hsv = basev * sq_r;
        float wsv = basev * sq_ir;
        float ax1 = cx - wsv * 0.5f;
        float ay1 = cy - hsv * 0.5f;

        float t1 = pr0 + ax1;
        float t2 = pr1 + ay1;
        float rx1 = fminf(fmaxf(t1, 0.0f), 799.0f);
        float ry1 = fminf(fmaxf(t2, 0.0f), 799.0f);
        float rx2 = fminf(fmaxf((t1 + pr2) + wsv, 0.0f), 799.0f);
        float ry2 = fminf(fmaxf((t2 + pr3) + hsv, 0.0f), 799.0f);

        float wv = pr2 + wsv, hv = pr3 + hsv;
        bool valid = (wv >= 16.0f) && (hv >= 16.0f);
        float sm = valid ? score : -INFINITY;

        unsigned u = __float_as_uint(sm);
        u = (u & 0x80000000u) ? ~u : (u | 0x80000000u);   // ascending-order map
        int gi = s * 9 + a;
        g_keys[gi] = ((unsigned long long)(~u) << 32) | (unsigned)gi; // asc key = desc score, stable
        g_boxes[gi] = make_float4(rx1, ry1, rx2, ry2);
    }
}

// ---------------------------------------------------------------------------
// Exact stable rank via O(N^2) counting; scatter top-6000 boxes in rank order.
// ---------------------------------------------------------------------------
__global__ void __launch_bounds__(256) rank_kernel() {
    const int i = blockIdx.x * 256 + threadIdx.x;
    __shared__ unsigned long long tile[1024];
    unsigned long long mykey = (i < NKEYS) ? g_keys[i] : 0xFFFFFFFFFFFFFFFFull;
    int rank = 0;
    for (int base = 0; base < NKEYS; base += 1024) {
        int m = min(1024, NKEYS - base);
        __syncthreads();
        for (int t = threadIdx.x; t < m; t += 256) tile[t] = g_keys[base + t];
        __syncthreads();
#pragma unroll 16
        for (int k = 0; k < m; ++k) rank += (tile[k] < mykey) ? 1 : 0;
    }
    if (i < NKEYS && rank < PRE_NMS) g_sboxes[rank] = g_boxes[i];
}

// ---------------------------------------------------------------------------
// NMS suppression mask — replicates the reference's buggy yy2 = MAX(y2_i, y2_j).
// mask[i][wj] bit b set  <=>  j = wj*32+b, j > i, ov(i,j) > 0.7
// ---------------------------------------------------------------------------
__global__ void __launch_bounds__(32) mask_kernel() {
    const int bi = blockIdx.y, bj = blockIdx.x;
    const int t = threadIdx.x;
    const int i = bi * 32 + t;
    if (bj < bi) { if (i < PRE_NMS) g_mask[i * NWORDS + bj] = 0u; return; }

    __shared__ float4 bx[32];
    __shared__ float ar[32];
    const int j0 = bj * 32;
    if (j0 + t < PRE_NMS) {
        float4 b = g_sboxes[j0 + t];
        bx[t] = b;
        ar[t] = ((b.z - b.x) + 1.0f) * ((b.w - b.y) + 1.0f);
    }
    __syncwarp();
    if (i >= PRE_NMS) return;

    float4 bi4 = g_sboxes[i];
    float areai = ((bi4.z - bi4.x) + 1.0f) * ((bi4.w - bi4.y) + 1.0f);
    unsigned word = 0;
    int jmax = min(32, PRE_NMS - j0);
    for (int jj = 0; jj < jmax; ++jj) {
        int jg = j0 + jj;
        if (jg <= i) continue;
        float4 bj4 = bx[jj];
        float xx1 = fmaxf(bi4.x, bj4.x);
        float yy1 = fmaxf(bi4.y, bj4.y);
        float xx2 = fminf(bi4.z, bj4.z);
        float yy2 = fmaxf(bi4.w, bj4.w);              // reference bug: max, not min
        float w = fmaxf(0.0f, (xx2 - xx1) + 1.0f);
        float h = fmaxf(0.0f, (yy2 - yy1) + 1.0f);
        float inter = w * h;
        float ov = inter / ((areai + ar[jj]) - inter);
        if (ov > 0.7f) word |= (1u << jj);
    }
    g_mask[i * NWORDS + bj] = word;
}

// ---------------------------------------------------------------------------
// Sequential keep-scan (single block) + stable selection + output.
// ---------------------------------------------------------------------------
__global__ void __launch_bounds__(256) scan_kernel(float* __restrict__ out) {
    __shared__ unsigned keep[NWORDS];
    __shared__ int pref[NWORDS + 1];
    const int tid = threadIdx.x;
    if (tid < NWORDS) keep[tid] = (tid == NWORDS - 1) ? 0x0000FFFFu : 0xFFFFFFFFu;
    __syncthreads();

    for (int wI = 0; wI < NWORDS; ++wI) {
        unsigned kw = keep[wI];
        __syncthreads();
        int nb = (wI == NWORDS - 1) ? 16 : 32;
        for (int b = 0; b < nb; ++b) {
            if (!((kw >> b) & 1u)) continue;           // uniform across block
            int i = wI * 32 + b;
            const unsigned* mrow = &g_mask[i * NWORDS];
            for (int w2 = wI + tid; w2 < NWORDS; w2 += 256) keep[w2] &= ~mrow[w2];
            __syncthreads();
            kw = keep[wI];
            __syncthreads();
        }
    }
    __syncthreads();

    if (tid == 0) {
        int run = 0;
        pref[0] = 0;
        for (int w = 0; w < NWORDS; ++w) { run += __popc(keep[w]); pref[w + 1] = run; }
    }
    __syncthreads();
    const int K = pref[NWORDS];

    for (int i = tid; i < PRE_NMS; i += 256) {
        int w = i >> 5, b = i & 31;
        unsigned kwv = keep[w];
        int kp = pref[w] + __popc(kwv & ((1u << b) - 1u));
        int pos = ((kwv >> b) & 1u) ? kp : (K + (i - kp));
        if (pos < POST_NMS) {
            float4 bb = g_sboxes[i];
            out[pos * 4 + 0] = bb.x;
            out[pos * 4 + 1] = bb.y;
            out[pos * 4 + 2] = (bb.z - bb.x) + 1.0f;
            out[pos * 4 + 3] = (bb.w - bb.y) + 1.0f;
        }
    }
}

// ---------------------------------------------------------------------------
extern "C" void kernel_launch(void* const* d_in, const int* in_sizes, int n_in,
                              void* d_out, int out_size) {
    const float* in_features = (const float*)d_in[0];
    const float* conv_w      = (const float*)d_in[1];
    const float* conv_b      = (const float*)d_in[2];
    const float* reg_w       = (const float*)d_in[3];
    const float* reg_b       = (const float*)d_in[4];
    const float* cls_w       = (const float*)d_in[5];
    const float* cls_b       = (const float*)d_in[6];
    float* out = (float*)d_out;

    pad_kernel<<<(NCH * XP * XP + 255) / 256, 256>>>(in_features);
    wt_kernel<<<(NCH * NCH * 9 + 255) / 256, 256>>>(conv_w);
    conv_kernel<<<dim3(8, 50), 160>>>(conv_b);
    head_kernel<<<FSZ * FSZ, 64>>>(reg_w, reg_b, cls_w, cls_b);
    rank_kernel<<<(NKEYS + 255) / 256, 256>>>();
    mask_kernel<<<dim3(NWORDS, NWORDS), 32>>>();
    scan_kernel<<<1, 256>>>(out);
}